// round 10
// baseline (speedup 1.0000x reference)
#include <cuda_runtime.h>
#include <cuda_fp16.h>
#include <math.h>
#include <stdint.h>

#define BB 128
#define TT 100
#define PD 4096
#define HG 512
#define HD 128
#define GH 261
#define GG 783
#define ZD 64
#define XD 256

__device__ __half g_projh[BB*TT*PD];   // fp16 activations (b*T+t, 4096)
__device__ __half g_Wih16[HG*PD];      // fp16 lstm_Wih
__device__ float g_xg[TT*BB*HG];       // (t,b,512)
__device__ float4 g_gWhh4[41*GG];      // gru Whh k=96..259: [p][g]
__device__ float4 g_W1T4[66*ZD];       // jf_W1 packs (zero-padded past 261)
__device__ float g_gxbase[BB*GG];

__device__ __forceinline__ float sigmoidf_(float x){ return 1.0f/(1.0f+expf(-x)); }
__device__ __forceinline__ float leakyf_(float x, float s){ return x >= 0.0f ? x : s*x; }
__device__ __forceinline__ void fma2(unsigned long long& a, unsigned long long w, unsigned long long h){
    asm("fma.rn.f32x2 %0, %1, %2, %0;" : "+l"(a) : "l"(w), "l"(h));
}
__device__ __forceinline__ void cp16(void* s, const void* g){
    unsigned ss = (unsigned)__cvta_generic_to_shared(s);
    asm volatile("cp.async.cg.shared.global [%0], [%1], 16;\n" :: "r"(ss), "l"(g));
}
#define MMA_F16(c, au, bu) \
  asm volatile("mma.sync.aligned.m16n8k16.row.col.f32.f16.f16.f32 " \
    "{%0,%1,%2,%3},{%4,%5,%6,%7},{%8,%9},{%0,%1,%2,%3};\n" \
    : "+f"(c[0]),"+f"(c[1]),"+f"(c[2]),"+f"(c[3]) \
    : "r"(au[0]),"r"(au[1]),"r"(au[2]),"r"(au[3]),"r"(bu[0]),"r"(bu[1]))
#define LDSM_X4(r0,r1,r2,r3, a) \
  asm volatile("ldmatrix.sync.aligned.m8n8.x4.shared.b16 {%0,%1,%2,%3}, [%4];" \
    : "=r"(r0),"=r"(r1),"=r"(r2),"=r"(r3) : "r"(a))
#define LDSM_X2(r0,r1, a) \
  asm volatile("ldmatrix.sync.aligned.m8n8.x2.shared.b16 {%0,%1}, [%2];" \
    : "=r"(r0),"=r"(r1) : "r"(a))

// K0: fp16 copy of lstm_Wih + float4 packs for gru Whh tail and jf_W1
__global__ void k_prep(const float* __restrict__ Wih,
                       const float* __restrict__ gWhh,
                       const float* __restrict__ W1)
{
    int i0 = blockIdx.x*blockDim.x + threadIdx.x;
    int st = gridDim.x*blockDim.x;
    for (int i = i0; i < HG*PD; i += st)
        g_Wih16[i] = __float2half_rn(Wih[i]);
    for (int i = i0; i < 41*GG; i += st){
        int p = i / GG, g = i - p*GG;
        const float* r = gWhh + (size_t)g*GH + 96 + 4*p;
        g_gWhh4[i] = make_float4(r[0], r[1], r[2], r[3]);
    }
    for (int i = i0; i < 66*ZD; i += st){
        int p = i >> 6, o = i & 63;
        const float* r = W1 + (size_t)o*GH;
        int k = 4*p;
        float4 v;
        v.x = (k   < GH) ? r[k]   : 0.f;
        v.y = (k+1 < GH) ? r[k+1] : 0.f;
        v.z = (k+2 < GH) ? r[k+2] : 0.f;
        v.w = (k+3 < GH) ? r[k+3] : 0.f;
        g_W1T4[i] = v;
    }
}

// K1: proj = fp16(leaky(pose @ proj_W^T + b)), 8 rows per block
__global__ void __launch_bounds__(512) k_proj(const float* __restrict__ pose,
                                              const float* __restrict__ W,
                                              const float* __restrict__ bias)
{
    __shared__ float p[8][9];
    int r0 = blockIdx.x*8;
    int tid = threadIdx.x;
    if (tid < 72) p[tid/9][tid%9] = pose[r0*9 + tid];
    __syncthreads();
#pragma unroll
    for (int i = 0; i < 8; i++){
        int k = tid + i*512;
        const float* w = W + k*9;
        float wv[9];
#pragma unroll
        for (int j = 0; j < 9; j++) wv[j] = w[j];
        float bk = bias[k];
#pragma unroll
        for (int r = 0; r < 8; r++){
            float acc = bk;
#pragma unroll
            for (int j = 0; j < 9; j++) acc += wv[j]*p[r][j];
            g_projh[(size_t)(r0+r)*PD + k] = __float2half_rn(leakyf_(acc, 0.1f));
        }
    }
}

// K2: fp16 mma.sync GEMM, 64x128 tiles (at scalar-pipe roofline; unchanged)
#define SMSH 72
#define KC 64
#define AROWS 64
#define BROWS 128
__global__ void __launch_bounds__(256, 3) k_gemm(const float* __restrict__ bih,
                                                 const float* __restrict__ bhh)
{
    extern __shared__ __align__(16) char smc[];
    __half* Ash = (__half*)smc;                           // [2][64][72]
    __half* Bsh = (__half*)(smc + 2*AROWS*SMSH*2);        // [2][128][72]
    uint32_t Au32 = (uint32_t)__cvta_generic_to_shared(Ash);
    uint32_t Bu32 = (uint32_t)__cvta_generic_to_shared(Bsh);
    int tid = threadIdx.x, lane = tid & 31, warp = tid >> 5;
    int bn = blockIdx.x, bm = blockIdx.y;
    const __half* Ag = g_projh + (size_t)bm*AROWS*PD;
    const __half* Bg = g_Wih16 + (size_t)bn*BROWS*PD;
    int wm = warp >> 2, wn = warp & 3;
    uint32_t aoff = ((uint32_t)(wm*32 + (lane & 15))*SMSH + (lane >> 4)*8) * 2;
    uint32_t boff = ((uint32_t)(wn*32 + (lane & 7))*SMSH + ((lane >> 3) & 1)*8) * 2;
    float acc[2][4][4];
#pragma unroll
    for (int a = 0; a < 2; a++)
#pragma unroll
        for (int b = 0; b < 4; b++)
#pragma unroll
            for (int c = 0; c < 4; c++) acc[a][b][c] = 0.f;

    for (int i = tid; i < 512; i += 256){
        int row = i >> 3, sub = i & 7;
        cp16(Ash + row*SMSH + sub*8, Ag + (size_t)row*PD + sub*8);
    }
    for (int i = tid; i < 1024; i += 256){
        int row = i >> 3, sub = i & 7;
        cp16(Bsh + row*SMSH + sub*8, Bg + (size_t)row*PD + sub*8);
    }
    asm volatile("cp.async.commit_group;\n");

    for (int c = 0; c < PD/KC; c++){
        int buf = c & 1;
        if (c+1 < PD/KC){
            int nb = buf^1;
            int kof = (c+1)*KC;
            for (int i = tid; i < 512; i += 256){
                int row = i >> 3, sub = i & 7;
                cp16(Ash + nb*AROWS*SMSH + row*SMSH + sub*8, Ag + (size_t)row*PD + kof + sub*8);
            }
            for (int i = tid; i < 1024; i += 256){
                int row = i >> 3, sub = i & 7;
                cp16(Bsh + nb*BROWS*SMSH + row*SMSH + sub*8, Bg + (size_t)row*PD + kof + sub*8);
            }
        }
        asm volatile("cp.async.commit_group;\n");
        asm volatile("cp.async.wait_group 1;\n");
        __syncthreads();
        uint32_t Ab = Au32 + (uint32_t)buf*AROWS*SMSH*2 + aoff;
        uint32_t Bb = Bu32 + (uint32_t)buf*BROWS*SMSH*2 + boff;
#pragma unroll
        for (int kk = 0; kk < 4; kk++){
            uint32_t au[2][4], bu[4][2];
#pragma unroll
            for (int mt = 0; mt < 2; mt++)
                LDSM_X4(au[mt][0], au[mt][1], au[mt][2], au[mt][3],
                        Ab + (uint32_t)(mt*16*SMSH + kk*16)*2);
#pragma unroll
            for (int nt = 0; nt < 4; nt++)
                LDSM_X2(bu[nt][0], bu[nt][1],
                        Bb + (uint32_t)(nt*8*SMSH + kk*16)*2);
#pragma unroll
            for (int mt = 0; mt < 2; mt++)
#pragma unroll
                for (int nt = 0; nt < 4; nt++)
                    MMA_F16(acc[mt][nt], au[mt], bu[nt]);
        }
        __syncthreads();
    }
#pragma unroll
    for (int mt = 0; mt < 2; mt++){
#pragma unroll
        for (int nt = 0; nt < 4; nt++){
            int col = bn*BROWS + wn*32 + nt*8 + (lane&3)*2;
            float bs0 = bih[col]   + bhh[col];
            float bs1 = bih[col+1] + bhh[col+1];
            int r0 = bm*AROWS + wm*32 + mt*16 + (lane>>2);
            int b0i = r0/TT, t0 = r0 - b0i*TT;
            *(float2*)(g_xg + (size_t)t0*(BB*HG) + b0i*HG + col) =
                make_float2(acc[mt][nt][0]+bs0, acc[mt][nt][1]+bs1);
            int r1 = r0 + 8;
            int b1i = r1/TT, t1 = r1 - b1i*TT;
            *(float2*)(g_xg + (size_t)t1*(BB*HG) + b1i*HG + col) =
                make_float2(acc[mt][nt][2]+bs0, acc[mt][nt][3]+bs1);
        }
    }
}

// K3: LSTM scan nb=2 (64 blocks, 2 batches/block, weight regs amortized)
// + fused VAE head / fc_in / static GRU input gates (replaces k_head).
__global__ void __launch_bounds__(512) k_lstm(
    const float* __restrict__ Whh,
    const float* __restrict__ eps,
    const float* __restrict__ muW, const float* __restrict__ mub,
    const float* __restrict__ lvW, const float* __restrict__ lvb,
    const float* __restrict__ fcW, const float* __restrict__ fcb,
    const float* __restrict__ gWih, const float* __restrict__ gbih,
    float* __restrict__ out)
{
    extern __shared__ float sm[];
    ulonglong2* wsu2 = (ulonglong2*)sm;          // [16][512]: k=64..127
    float* hs0 = sm + 32768;                     // 128
    float* hs1 = hs0 + 128;                      // 128
    float* gs  = hs1 + 128;                      // [2][512]
    float* mu_s = gs + 1024;                     // [2][64]
    float* lv_s = mu_s + 128;                    // [2][64]
    float* emb  = lv_s + 128;                    // [2][64]
    float* xs   = emb + 128;                     // [2][256]
    int tid = threadIdx.x;
    int b0 = blockIdx.x*2;

    const ulonglong2* wrow = (const ulonglong2*)(Whh + (size_t)tid*HD);
    unsigned long long wr2[32];
#pragma unroll
    for (int i = 0; i < 16; i++){
        ulonglong2 v = wrow[i];
        wr2[2*i] = v.x; wr2[2*i+1] = v.y;
    }
#pragma unroll
    for (int i = 0; i < 16; i++) wsu2[i*512 + tid] = wrow[16+i];
    if (tid < 2*HD){ hs0[tid & 127] = 0.f; hs1[tid & 127] = 0.f; }
    float c = 0.f;
    __syncthreads();
    const float* xg0 = g_xg + b0*HG + tid;
    const float* xg1 = xg0 + HG;
    float x0 = xg0[0], x1 = xg1[0];
    for (int t = 0; t < TT; t++){
        float x0n = (t < TT-1) ? xg0[(size_t)(t+1)*(BB*HG)] : 0.f;
        float x1n = (t < TT-1) ? xg1[(size_t)(t+1)*(BB*HG)] : 0.f;
        const ulonglong2* H0 = (const ulonglong2*)hs0;
        const ulonglong2* H1 = (const ulonglong2*)hs1;
        unsigned long long a0 = 0ull, d0 = 0ull, a1 = 0ull, d1 = 0ull;
#pragma unroll
        for (int i = 0; i < 16; i++){
            ulonglong2 h0 = H0[i], h1 = H1[i];
            fma2(a0, wr2[2*i],   h0.x);
            fma2(d0, wr2[2*i+1], h0.y);
            fma2(a1, wr2[2*i],   h1.x);
            fma2(d1, wr2[2*i+1], h1.y);
        }
#pragma unroll
        for (int i = 0; i < 16; i++){
            ulonglong2 w = wsu2[i*512 + tid];
            ulonglong2 h0 = H0[16+i], h1 = H1[16+i];
            fma2(a0, w.x, h0.x);
            fma2(d0, w.y, h0.y);
            fma2(a1, w.x, h1.x);
            fma2(d1, w.y, h1.y);
        }
        float p0,p1,q0,q1,r0,r1,s0,s1;
        asm("mov.b64 {%0,%1}, %2;" : "=f"(p0), "=f"(p1) : "l"(a0));
        asm("mov.b64 {%0,%1}, %2;" : "=f"(q0), "=f"(q1) : "l"(d0));
        asm("mov.b64 {%0,%1}, %2;" : "=f"(r0), "=f"(r1) : "l"(a1));
        asm("mov.b64 {%0,%1}, %2;" : "=f"(s0), "=f"(s1) : "l"(d1));
        gs[tid]       = x0 + (p0+p1) + (q0+q1);
        gs[512 + tid] = x1 + (r0+r1) + (s0+s1);
        __syncthreads();
        if (tid < 256){
            int bb = tid >> 7, j = tid & 127;
            const float* g = gs + bb*512;
            float* hb = bb ? hs1 : hs0;
            float ii = sigmoidf_(g[j]);
            float ff = sigmoidf_(g[HD+j]);
            float gg = tanhf(g[2*HD+j]);
            float oo = sigmoidf_(g[3*HD+j]);
            c = ff*c + ii*gg;
            hb[j] = oo*tanhf(c);
        }
        __syncthreads();
        x0 = x0n; x1 = x1n;
    }
    // ---- fused head (2 batches) ----
    if (tid < 256){
        int bb = tid >> 7, r = tid & 127, o = r & 63;
        const float* h = bb ? hs1 : hs0;
        const float* W = (r < 64) ? (muW + o*HD) : (lvW + o*HD);
        float acc = (r < 64) ? mub[o] : lvb[o];
        for (int k = 0; k < HD; k++) acc += W[k]*h[k];
        acc = leakyf_(acc, 0.1f);
        if (r < 64) mu_s[bb*64 + o] = acc;
        else        lv_s[bb*64 + o] = fminf(10.f, fmaxf(-10.f, acc));
    }
    __syncthreads();
    if (tid < 128){
        int bb = tid >> 6, o = tid & 63;
        int b = b0 + bb;
        float m = mu_s[bb*64 + o], lv = lv_s[bb*64 + o];
        out[BB*TT*9 + b*ZD + o] = m;
        out[BB*TT*9 + BB*ZD + b*ZD + o] = lv;
        emb[bb*64 + o] = m + eps[b*ZD + o]*expf(0.5f*lv);
    }
    __syncthreads();
    {
        int bb = tid >> 8, o = tid & 255;
        const float* e = emb + bb*64;
        float acc = fcb[o];
        const float* W = fcW + o*ZD;
        for (int k = 0; k < ZD; k++) acc += W[k]*e[k];
        xs[bb*256 + o] = acc;
    }
    __syncthreads();
    for (int idx = tid; idx < 2*GG; idx += 512){
        int bb = (idx < GG) ? 0 : 1;
        int g = idx - bb*GG;
        const float* x = xs + bb*256;
        float acc = gbih[g];
        const float* W = gWih + (size_t)g*GH;
        for (int k = 0; k < XD; k++) acc += W[k]*x[k];
        g_gxbase[(size_t)(b0+bb)*GG + g] = acc;
    }
}

// K5: GRU scan + pipelined jf head. 928 threads, 2 batches/block, 2 syncs/step.
__global__ void __launch_bounds__(928) k_gru(
    const float* __restrict__ noise_eps,
    const float* __restrict__ gWih, const float* __restrict__ gWhh,
    const float* __restrict__ gbhh,
    const float* __restrict__ b1,
    const float* __restrict__ W2, const float* __restrict__ b2,
    float* __restrict__ out)
{
    extern __shared__ float sm[];
    ulonglong2* wsA = (ulonglong2*)sm;   // [16][784]: k=32..95 pair-pairs
    float* hb0  = sm + 50176;            // 264 (zero-padded)
    float* hb1  = hb0 + 264;
    float* sums = hb1 + 264;             // [2][784]
    float* ghn  = sums + 2*784;          // [2][264]
    float* f1s  = ghn + 2*264;           // [2][64]
    float* nsAll= f1s + 128;             // [TT][8]
    int tid = threadIdx.x;
    int b0 = blockIdx.x*2;

    for (int j = tid; j < 528; j += 928) hb0[j] = 0.f;
    for (int j = tid; j < TT*8; j += 928){
        int t = j >> 3, r = j & 7, bb = r >> 2, jj = r & 3;
        nsAll[j] = noise_eps[t*(BB*4) + (b0+bb)*4 + jj] * 0.1f;
    }

    unsigned long long wr2[16];
    float w260=0,wn0=0,wn1=0,wn2=0,wn3=0,wt=0,bh=0,gx0b=0,gx1b=0;
    if (tid < GG){
        const float* row = gWhh + (size_t)tid*GH;
#pragma unroll
        for (int i = 0; i < 16; i++)
            asm("mov.b64 %0, {%1,%2};" : "=l"(wr2[i]) : "f"(row[2*i]), "f"(row[2*i+1]));
#pragma unroll
        for (int i = 0; i < 16; i++){
            ulonglong2 w;
            asm("mov.b64 %0, {%1,%2};" : "=l"(w.x) : "f"(row[32+4*i]), "f"(row[33+4*i]));
            asm("mov.b64 %0, {%1,%2};" : "=l"(w.y) : "f"(row[34+4*i]), "f"(row[35+4*i]));
            wsA[i*784 + tid] = w;
        }
        w260 = row[260];
        const float* Wi = gWih + (size_t)tid*GH;
        wn0=Wi[256]; wn1=Wi[257]; wn2=Wi[258]; wn3=Wi[259]; wt=Wi[260];
        bh = gbhh[tid];
        gx0b = g_gxbase[b0*GG + tid];
        gx1b = g_gxbase[(b0+1)*GG + tid];
    }
    __syncthreads();
    const float inv = 1.0f/(float)(TT-1);
    for (int t = 0; t <= TT; t++){
        // ---- P1: matvec(t) || f1-head(t-1)
        if (t < TT && tid < GG){
            const float* nsp = nsAll + t*8;
            float tv = (float)t * inv;
            float gx0 = gx0b + wn0*nsp[0]+wn1*nsp[1]+wn2*nsp[2]+wn3*nsp[3] + wt*tv;
            float gx1 = gx1b + wn0*nsp[4]+wn1*nsp[5]+wn2*nsp[6]+wn3*nsp[7] + wt*tv;
            unsigned long long a0p = 0ull, a1p = 0ull;
            const ulonglong2* H0 = (const ulonglong2*)hb0;
            const ulonglong2* H1 = (const ulonglong2*)hb1;
#pragma unroll
            for (int i = 0; i < 8; i++){
                ulonglong2 h0 = H0[i], h1 = H1[i];
                fma2(a0p, wr2[2*i],   h0.x);  fma2(a1p, wr2[2*i],   h1.x);
                fma2(a0p, wr2[2*i+1], h0.y);  fma2(a1p, wr2[2*i+1], h1.y);
            }
#pragma unroll
            for (int i = 0; i < 16; i++){
                ulonglong2 w = wsA[i*784 + tid];
                ulonglong2 h0 = H0[8+i], h1 = H1[8+i];
                fma2(a0p, w.x, h0.x);  fma2(a1p, w.x, h1.x);
                fma2(a0p, w.y, h0.y);  fma2(a1p, w.y, h1.y);
            }
            const ulonglong2* wp = (const ulonglong2*)g_gWhh4 + tid;
#pragma unroll 8
            for (int p = 0; p < 41; p++){
                ulonglong2 w = wp[(size_t)p*GG];
                ulonglong2 h0 = H0[24+p], h1 = H1[24+p];
                fma2(a0p, w.x, h0.x);  fma2(a1p, w.x, h1.x);
                fma2(a0p, w.y, h0.y);  fma2(a1p, w.y, h1.y);
            }
            float s00,s01,s10,s11;
            asm("mov.b64 {%0,%1}, %2;" : "=f"(s00), "=f"(s01) : "l"(a0p));
            asm("mov.b64 {%0,%1}, %2;" : "=f"(s10), "=f"(s11) : "l"(a1p));
            float gh0 = bh + (s00+s01) + w260*hb0[260];
            float gh1 = bh + (s10+s11) + w260*hb1[260];
            float v0 = gx0 + gh0, v1 = gx1 + gh1;
            if (tid >= 522){
                v0 = gx0; v1 = gx1;
                ghn[tid-522] = gh0; ghn[264 + tid-522] = gh1;
            }
            sums[tid] = v0; sums[784 + tid] = v1;
        }
        if (t >= 1 && tid >= 800){
            int q = tid - 800, bb = q >> 6, o = q & 63;
            const float4* hv = (const float4*)(bb ? hb1 : hb0);
            const float4* Wv = g_W1T4 + o;
            float acc = b1[o];
#pragma unroll
            for (int p = 0; p < 66; p++){
                float4 w = Wv[p*ZD];
                float4 h = hv[p];
                acc += w.x*h.x + w.y*h.y + w.z*h.z + w.w*h.w;
            }
            f1s[bb*64 + o] = leakyf_(acc, 0.2f);
        }
        __syncthreads();
        // ---- P2: gates/update(t) || frame(t-1)
        if (t < TT && tid < 522){
            int bb = tid/261, j = tid - bb*261;
            float* hb = bb ? hb1 : hb0;
            const float* s = sums + bb*784;
            float r = sigmoidf_(s[j]);
            float z = sigmoidf_(s[261+j]);
            float n = tanhf(s[522+j] + r*ghn[bb*264 + j]);
            hb[j] = (1.f - z)*n + z*hb[j];
        }
        if (t >= 1 && tid >= 800 && tid < 818){
            int q = tid - 800, bb = q/9, i = q - bb*9;
            float acc = b2[i];
            const float* W = W2 + i*ZD;
            for (int o = 0; o < ZD; o++) acc += W[o]*f1s[bb*64 + o];
            out[(size_t)(b0+bb)*(TT*9) + (t-1)*9 + i] = sigmoidf_(acc);
        }
        __syncthreads();
    }
}

extern "C" void kernel_launch(void* const* d_in, const int* in_sizes, int n_in,
                              void* d_out, int out_size)
{
    const float* input_data = (const float*)d_in[0];
    const float* eps        = (const float*)d_in[1];
    const float* noise_eps  = (const float*)d_in[2];
    const float* proj_W     = (const float*)d_in[3];
    const float* proj_b     = (const float*)d_in[4];
    const float* lstm_Wih   = (const float*)d_in[5];
    const float* lstm_Whh   = (const float*)d_in[6];
    const float* lstm_bih   = (const float*)d_in[7];
    const float* lstm_bhh   = (const float*)d_in[8];
    const float* mu_W       = (const float*)d_in[9];
    const float* mu_b       = (const float*)d_in[10];
    const float* lv_W       = (const float*)d_in[11];
    const float* lv_b       = (const float*)d_in[12];
    const float* fcin_W     = (const float*)d_in[13];
    const float* fcin_b     = (const float*)d_in[14];
    const float* gru_Wih    = (const float*)d_in[15];
    const float* gru_Whh    = (const float*)d_in[16];
    const float* gru_bih    = (const float*)d_in[17];
    const float* gru_bhh    = (const float*)d_in[18];
    const float* jf_W1      = (const float*)d_in[19];
    const float* jf_b1      = (const float*)d_in[20];
    const float* jf_W2      = (const float*)d_in[21];
    const float* jf_b2      = (const float*)d_in[22];
    float* out = (float*)d_out;

    int gemm_smem = (2*AROWS*SMSH + 2*BROWS*SMSH)*2;
    int lstm_smem = 32768*4 + (256 + 1024 + 128 + 128 + 128 + 512)*4;
    int gru_smem  = (50176 + 264 + 264 + 2*784 + 2*264 + 128 + TT*8)*4;
    cudaFuncSetAttribute(k_gemm, cudaFuncAttributeMaxDynamicSharedMemorySize, gemm_smem);
    cudaFuncSetAttribute(k_lstm, cudaFuncAttributeMaxDynamicSharedMemorySize, lstm_smem);
    cudaFuncSetAttribute(k_gru,  cudaFuncAttributeMaxDynamicSharedMemorySize, gru_smem);

    k_prep<<<160, 256>>>(lstm_Wih, gru_Whh, jf_W1);
    k_proj<<<BB*TT/8, 512>>>(input_data, proj_W, proj_b);
    dim3 g2(HG/BROWS, TT*BB/AROWS);   // (4, 200) = 800 CTAs
    k_gemm<<<g2, 256, gemm_smem>>>(lstm_bih, lstm_bhh);
    k_lstm<<<BB/2, 512, lstm_smem>>>(lstm_Whh, eps, mu_W, mu_b, lv_W, lv_b,
                                     fcin_W, fcin_b, gru_Wih, gru_bih, out);
    k_gru<<<BB/2, 928, gru_smem>>>(noise_eps, gru_Wih, gru_Whh, gru_bhh,
                                   jf_b1, jf_W2, jf_b2, out);
}

// round 11
// speedup vs baseline: 1.0830x; 1.0830x over previous
#include <cuda_runtime.h>
#include <cuda_fp16.h>
#include <math.h>
#include <stdint.h>

#define BB 128
#define TT 100
#define PD 4096
#define HG 512
#define HD 128
#define GH 261
#define GG 783
#define ZD 64
#define XD 256

__device__ __half g_projh[BB*TT*PD];   // fp16 activations (b*T+t, 4096)
__device__ __half g_Wih16[HG*PD];      // fp16 lstm_Wih
__device__ float g_xg[TT*BB*HG];       // (t,b,512)
__device__ float4 g_gWhh4[41*GG];      // gru Whh k=96..259: [p][g]
__device__ float4 g_W1T4[66*ZD];       // jf_W1 packs (zero-padded past 261)
__device__ float g_gxbase[BB*GG];

__device__ __forceinline__ float sigmoidf_(float x){ return 1.0f/(1.0f+expf(-x)); }
__device__ __forceinline__ float leakyf_(float x, float s){ return x >= 0.0f ? x : s*x; }
__device__ __forceinline__ void fma2(unsigned long long& a, unsigned long long w, unsigned long long h){
    asm("fma.rn.f32x2 %0, %1, %2, %0;" : "+l"(a) : "l"(w), "l"(h));
}
__device__ __forceinline__ void cp16(void* s, const void* g){
    unsigned ss = (unsigned)__cvta_generic_to_shared(s);
    asm volatile("cp.async.cg.shared.global [%0], [%1], 16;\n" :: "r"(ss), "l"(g));
}
#define MMA_F16(c, au, bu) \
  asm volatile("mma.sync.aligned.m16n8k16.row.col.f32.f16.f16.f32 " \
    "{%0,%1,%2,%3},{%4,%5,%6,%7},{%8,%9},{%0,%1,%2,%3};\n" \
    : "+f"(c[0]),"+f"(c[1]),"+f"(c[2]),"+f"(c[3]) \
    : "r"(au[0]),"r"(au[1]),"r"(au[2]),"r"(au[3]),"r"(bu[0]),"r"(bu[1]))

// K0: fp16 copy of lstm_Wih + float4 packs for gru Whh tail and jf_W1
__global__ void k_prep(const float* __restrict__ Wih,
                       const float* __restrict__ gWhh,
                       const float* __restrict__ W1)
{
    int i0 = blockIdx.x*blockDim.x + threadIdx.x;
    int st = gridDim.x*blockDim.x;
    for (int i = i0; i < HG*PD; i += st)
        g_Wih16[i] = __float2half_rn(Wih[i]);
    for (int i = i0; i < 41*GG; i += st){
        int p = i / GG, g = i - p*GG;
        const float* r = gWhh + (size_t)g*GH + 96 + 4*p;
        g_gWhh4[i] = make_float4(r[0], r[1], r[2], r[3]);
    }
    for (int i = i0; i < 66*ZD; i += st){
        int p = i >> 6, o = i & 63;
        const float* r = W1 + (size_t)o*GH;
        int k = 4*p;
        float4 v;
        v.x = (k   < GH) ? r[k]   : 0.f;
        v.y = (k+1 < GH) ? r[k+1] : 0.f;
        v.z = (k+2 < GH) ? r[k+2] : 0.f;
        v.w = (k+3 < GH) ? r[k+3] : 0.f;
        g_W1T4[i] = v;
    }
}

// K1: proj = fp16(leaky(pose @ proj_W^T + b)), 8 rows per block
__global__ void __launch_bounds__(512) k_proj(const float* __restrict__ pose,
                                              const float* __restrict__ W,
                                              const float* __restrict__ bias)
{
    __shared__ float p[8][9];
    int r0 = blockIdx.x*8;
    int tid = threadIdx.x;
    if (tid < 72) p[tid/9][tid%9] = pose[r0*9 + tid];
    __syncthreads();
#pragma unroll
    for (int i = 0; i < 8; i++){
        int k = tid + i*512;
        const float* w = W + k*9;
        float wv[9];
#pragma unroll
        for (int j = 0; j < 9; j++) wv[j] = w[j];
        float bk = bias[k];
#pragma unroll
        for (int r = 0; r < 8; r++){
            float acc = bk;
#pragma unroll
            for (int j = 0; j < 9; j++) acc += wv[j]*p[r][j];
            g_projh[(size_t)(r0+r)*PD + k] = __float2half_rn(leakyf_(acc, 0.1f));
        }
    }
}

// K2: fp16 mma.sync GEMM: x_gates = proj @ Wih^T + bih + bhh -> (t,b,g)
#define SMSH 72
#define KC 64
__global__ void __launch_bounds__(256, 2) k_gemm(const float* __restrict__ bih,
                                                 const float* __restrict__ bhh)
{
    extern __shared__ __align__(16) char smc[];
    __half* Ash = (__half*)smc;                       // [2][128][72]
    __half* Bsh = (__half*)(smc + 2*128*SMSH*2);      // [2][128][72]
    int tid = threadIdx.x, lane = tid & 31, warp = tid >> 5;
    int bn = blockIdx.x, bm = blockIdx.y;
    const __half* Ag = g_projh + (size_t)bm*128*PD;
    const __half* Bg = g_Wih16 + (size_t)bn*128*PD;
    int wm = warp >> 2, wn = warp & 3;
    float acc[4][4][4];
#pragma unroll
    for (int a = 0; a < 4; a++)
#pragma unroll
        for (int b = 0; b < 4; b++)
#pragma unroll
            for (int c = 0; c < 4; c++) acc[a][b][c] = 0.f;

    for (int i = tid; i < 1024; i += 256){
        int row = i >> 3, sub = i & 7;
        cp16(Ash + row*SMSH + sub*8, Ag + (size_t)row*PD + sub*8);
    }
    for (int i = tid; i < 1024; i += 256){
        int row = i >> 3, sub = i & 7;
        cp16(Bsh + row*SMSH + sub*8, Bg + (size_t)row*PD + sub*8);
    }
    asm volatile("cp.async.commit_group;\n");

    for (int c = 0; c < PD/KC; c++){
        int buf = c & 1;
        if (c+1 < PD/KC){
            int nb = buf^1;
            int kof = (c+1)*KC;
            for (int i = tid; i < 1024; i += 256){
                int row = i >> 3, sub = i & 7;
                cp16(Ash + nb*128*SMSH + row*SMSH + sub*8, Ag + (size_t)row*PD + kof + sub*8);
            }
            for (int i = tid; i < 1024; i += 256){
                int row = i >> 3, sub = i & 7;
                cp16(Bsh + nb*128*SMSH + row*SMSH + sub*8, Bg + (size_t)row*PD + kof + sub*8);
            }
        }
        asm volatile("cp.async.commit_group;\n");
        asm volatile("cp.async.wait_group 1;\n");
        __syncthreads();
        const uint32_t* A = (const uint32_t*)(Ash + buf*128*SMSH);
        const uint32_t* B = (const uint32_t*)(Bsh + buf*128*SMSH);
#pragma unroll
        for (int kk = 0; kk < 4; kk++){
            int kw = kk*8 + (lane & 3);
            uint32_t au[4][4], bu[4][2];
#pragma unroll
            for (int mt = 0; mt < 4; mt++){
                int r = wm*64 + mt*16 + (lane>>2);
                au[mt][0] = A[r*36 + kw];
                au[mt][1] = A[(r+8)*36 + kw];
                au[mt][2] = A[r*36 + kw + 4];
                au[mt][3] = A[(r+8)*36 + kw + 4];
            }
#pragma unroll
            for (int nt = 0; nt < 4; nt++){
                int n = wn*32 + nt*8 + (lane>>2);
                bu[nt][0] = B[n*36 + kw];
                bu[nt][1] = B[n*36 + kw + 4];
            }
#pragma unroll
            for (int mt = 0; mt < 4; mt++)
#pragma unroll
                for (int nt = 0; nt < 4; nt++)
                    MMA_F16(acc[mt][nt], au[mt], bu[nt]);
        }
        __syncthreads();
    }
#pragma unroll
    for (int mt = 0; mt < 4; mt++){
#pragma unroll
        for (int nt = 0; nt < 4; nt++){
            int col = bn*128 + wn*32 + nt*8 + (lane&3)*2;
            float bs0 = bih[col]   + bhh[col];
            float bs1 = bih[col+1] + bhh[col+1];
            int r0 = bm*128 + wm*64 + mt*16 + (lane>>2);
            int b0i = r0/TT, t0 = r0 - b0i*TT;
            *(float2*)(g_xg + (size_t)t0*(BB*HG) + b0i*HG + col) =
                make_float2(acc[mt][nt][0]+bs0, acc[mt][nt][1]+bs1);
            int r1 = r0 + 8;
            int b1i = r1/TT, t1 = r1 - b1i*TT;
            *(float2*)(g_xg + (size_t)t1*(BB*HG) + b1i*HG + col) =
                make_float2(acc[mt][nt][2]+bs0, acc[mt][nt][3]+bs1);
        }
    }
}

// K3: LSTM scan nb=1 (128 blocks) with parallel gate activations (512 threads)
// + fused VAE head / fc_in / static GRU input gates.
__global__ void __launch_bounds__(512) k_lstm(
    const float* __restrict__ Whh,
    const float* __restrict__ eps,
    const float* __restrict__ muW, const float* __restrict__ mub,
    const float* __restrict__ lvW, const float* __restrict__ lvb,
    const float* __restrict__ fcW, const float* __restrict__ fcb,
    const float* __restrict__ gWih, const float* __restrict__ gbih,
    float* __restrict__ out)
{
    extern __shared__ float sm[];
    ulonglong2* wsu2 = (ulonglong2*)sm;          // [16][512]: k=64..127
    float* hs = sm + 32768;                      // 128
    float* gs = hs + 128;                        // 512
    float* mu_s = gs + 512;                      // 64
    float* lv_s = mu_s + 64;                     // 64
    float* emb  = lv_s + 64;                     // 64
    float* xs   = emb + 64;                      // 256
    int tid = threadIdx.x, b = blockIdx.x;

    const ulonglong2* wrow = (const ulonglong2*)(Whh + (size_t)tid*HD);
    unsigned long long wr2[32];
#pragma unroll
    for (int i = 0; i < 16; i++){
        ulonglong2 v = wrow[i];
        wr2[2*i] = v.x; wr2[2*i+1] = v.y;
    }
#pragma unroll
    for (int i = 0; i < 16; i++) wsu2[i*512 + tid] = wrow[16+i];
    if (tid < HD) hs[tid] = 0.f;
    float c = 0.f;
    __syncthreads();
    const float* xg = g_xg + b*HG + tid;
    float xcur = xg[0];
    for (int t = 0; t < TT; t++){
        float xnext = (t < TT-1) ? xg[(size_t)(t+1)*(BB*HG)] : 0.f;
        const ulonglong2* H2 = (const ulonglong2*)hs;
        unsigned long long a2 = 0ull, c2 = 0ull, d2 = 0ull, e2 = 0ull;
#pragma unroll
        for (int i = 0; i < 8; i++){
            ulonglong2 h0 = H2[2*i], h1 = H2[2*i+1];
            fma2(a2, wr2[4*i],   h0.x);
            fma2(c2, wr2[4*i+1], h0.y);
            fma2(d2, wr2[4*i+2], h1.x);
            fma2(e2, wr2[4*i+3], h1.y);
        }
#pragma unroll
        for (int i = 0; i < 8; i++){
            ulonglong2 w0 = wsu2[(2*i)*512 + tid];
            ulonglong2 w1 = wsu2[(2*i+1)*512 + tid];
            ulonglong2 h0 = H2[16+2*i], h1 = H2[17+2*i];
            fma2(a2, w0.x, h0.x);
            fma2(c2, w0.y, h0.y);
            fma2(d2, w1.x, h1.x);
            fma2(e2, w1.y, h1.y);
        }
        float a0,a1,b0,b1,d0,d1,e0,e1;
        asm("mov.b64 {%0,%1}, %2;" : "=f"(a0), "=f"(a1) : "l"(a2));
        asm("mov.b64 {%0,%1}, %2;" : "=f"(b0), "=f"(b1) : "l"(c2));
        asm("mov.b64 {%0,%1}, %2;" : "=f"(d0), "=f"(d1) : "l"(d2));
        asm("mov.b64 {%0,%1}, %2;" : "=f"(e0), "=f"(e1) : "l"(e2));
        gs[tid] = xcur + ((a0+a1) + (b0+b1)) + ((d0+d1) + (e0+e1));
        __syncthreads();
        // one activation per thread: i,f (sigmoid), g (tanh), o (sigmoid)
        {
            float v = gs[tid];
            gs[tid] = (tid >= 2*HD && tid < 3*HD) ? tanhf(v) : sigmoidf_(v);
        }
        __syncthreads();
        if (tid < HD){
            c = gs[HD+tid]*c + gs[tid]*gs[2*HD+tid];
            hs[tid] = gs[3*HD+tid]*tanhf(c);
        }
        __syncthreads();
        xcur = xnext;
    }
    // ---- fused head (batch b) ----
    if (tid < 2*ZD){
        int o = tid & 63;
        const float* W = (tid < ZD) ? (muW + o*HD) : (lvW + o*HD);
        float acc = (tid < ZD) ? mub[o] : lvb[o];
        for (int k = 0; k < HD; k++) acc += W[k]*hs[k];
        acc = leakyf_(acc, 0.1f);
        if (tid < ZD) mu_s[o] = acc;
        else          lv_s[o] = fminf(10.f, fmaxf(-10.f, acc));
    }
    __syncthreads();
    if (tid < ZD){
        float m = mu_s[tid], lv = lv_s[tid];
        out[BB*TT*9 + b*ZD + tid] = m;
        out[BB*TT*9 + BB*ZD + b*ZD + tid] = lv;
        emb[tid] = m + eps[b*ZD + tid]*expf(0.5f*lv);
    }
    __syncthreads();
    if (tid < XD){
        float acc = fcb[tid];
        const float* W = fcW + tid*ZD;
        for (int k = 0; k < ZD; k++) acc += W[k]*emb[k];
        xs[tid] = acc;
    }
    __syncthreads();
    for (int g = tid; g < GG; g += 512){
        float acc = gbih[g];
        const float* W = gWih + (size_t)g*GH;
        for (int k = 0; k < XD; k++) acc += W[k]*xs[k];
        g_gxbase[(size_t)b*GG + g] = acc;
    }
}

// K5: GRU scan + pipelined jf head. 928 threads, 2 batches/block, 2 syncs/step.
__global__ void __launch_bounds__(928) k_gru(
    const float* __restrict__ noise_eps,
    const float* __restrict__ gWih, const float* __restrict__ gWhh,
    const float* __restrict__ gbhh,
    const float* __restrict__ b1,
    const float* __restrict__ W2, const float* __restrict__ b2,
    float* __restrict__ out)
{
    extern __shared__ float sm[];
    ulonglong2* wsA = (ulonglong2*)sm;   // [16][784]: k=32..95 pair-pairs
    float* hb0  = sm + 50176;            // 264 (zero-padded)
    float* hb1  = hb0 + 264;
    float* sums = hb1 + 264;             // [2][784]
    float* ghn  = sums + 2*784;          // [2][264]
    float* f1s  = ghn + 2*264;           // [2][64]
    float* nsAll= f1s + 128;             // [TT][8]
    int tid = threadIdx.x;
    int b0 = blockIdx.x*2;

    for (int j = tid; j < 528; j += 928) hb0[j] = 0.f;
    for (int j = tid; j < TT*8; j += 928){
        int t = j >> 3, r = j & 7, bb = r >> 2, jj = r & 3;
        nsAll[j] = noise_eps[t*(BB*4) + (b0+bb)*4 + jj] * 0.1f;
    }

    unsigned long long wr2[16];
    float w260=0,wn0=0,wn1=0,wn2=0,wn3=0,wt=0,bh=0,gx0b=0,gx1b=0;
    if (tid < GG){
        const float* row = gWhh + (size_t)tid*GH;
#pragma unroll
        for (int i = 0; i < 16; i++)
            asm("mov.b64 %0, {%1,%2};" : "=l"(wr2[i]) : "f"(row[2*i]), "f"(row[2*i+1]));
#pragma unroll
        for (int i = 0; i < 16; i++){
            ulonglong2 w;
            asm("mov.b64 %0, {%1,%2};" : "=l"(w.x) : "f"(row[32+4*i]), "f"(row[33+4*i]));
            asm("mov.b64 %0, {%1,%2};" : "=l"(w.y) : "f"(row[34+4*i]), "f"(row[35+4*i]));
            wsA[i*784 + tid] = w;
        }
        w260 = row[260];
        const float* Wi = gWih + (size_t)tid*GH;
        wn0=Wi[256]; wn1=Wi[257]; wn2=Wi[258]; wn3=Wi[259]; wt=Wi[260];
        bh = gbhh[tid];
        gx0b = g_gxbase[b0*GG + tid];
        gx1b = g_gxbase[(b0+1)*GG + tid];
    }
    __syncthreads();
    const float inv = 1.0f/(float)(TT-1);
    for (int t = 0; t <= TT; t++){
        // ---- P1: matvec(t) || f1-head(t-1)
        if (t < TT && tid < GG){
            const float* nsp = nsAll + t*8;
            float tv = (float)t * inv;
            float gx0 = gx0b + wn0*nsp[0]+wn1*nsp[1]+wn2*nsp[2]+wn3*nsp[3] + wt*tv;
            float gx1 = gx1b + wn0*nsp[4]+wn1*nsp[5]+wn2*nsp[6]+wn3*nsp[7] + wt*tv;
            unsigned long long a0p = 0ull, a1p = 0ull;
            const ulonglong2* H0 = (const ulonglong2*)hb0;
            const ulonglong2* H1 = (const ulonglong2*)hb1;
#pragma unroll
            for (int i = 0; i < 8; i++){
                ulonglong2 h0 = H0[i], h1 = H1[i];
                fma2(a0p, wr2[2*i],   h0.x);  fma2(a1p, wr2[2*i],   h1.x);
                fma2(a0p, wr2[2*i+1], h0.y);  fma2(a1p, wr2[2*i+1], h1.y);
            }
#pragma unroll
            for (int i = 0; i < 16; i++){
                ulonglong2 w = wsA[i*784 + tid];
                ulonglong2 h0 = H0[8+i], h1 = H1[8+i];
                fma2(a0p, w.x, h0.x);  fma2(a1p, w.x, h1.x);
                fma2(a0p, w.y, h0.y);  fma2(a1p, w.y, h1.y);
            }
            const ulonglong2* wp = (const ulonglong2*)g_gWhh4 + tid;
#pragma unroll 8
            for (int p = 0; p < 41; p++){
                ulonglong2 w = wp[(size_t)p*GG];
                ulonglong2 h0 = H0[24+p], h1 = H1[24+p];
                fma2(a0p, w.x, h0.x);  fma2(a1p, w.x, h1.x);
                fma2(a0p, w.y, h0.y);  fma2(a1p, w.y, h1.y);
            }
            float s00,s01,s10,s11;
            asm("mov.b64 {%0,%1}, %2;" : "=f"(s00), "=f"(s01) : "l"(a0p));
            asm("mov.b64 {%0,%1}, %2;" : "=f"(s10), "=f"(s11) : "l"(a1p));
            float gh0 = bh + (s00+s01) + w260*hb0[260];
            float gh1 = bh + (s10+s11) + w260*hb1[260];
            float v0 = gx0 + gh0, v1 = gx1 + gh1;
            if (tid >= 522){
                v0 = gx0; v1 = gx1;
                ghn[tid-522] = gh0; ghn[264 + tid-522] = gh1;
            }
            sums[tid] = v0; sums[784 + tid] = v1;
        }
        if (t >= 1 && tid >= 800){
            int q = tid - 800, bb = q >> 6, o = q & 63;
            const float4* hv = (const float4*)(bb ? hb1 : hb0);
            const float4* Wv = g_W1T4 + o;
            float acc = b1[o];
#pragma unroll
            for (int p = 0; p < 66; p++){
                float4 w = Wv[p*ZD];
                float4 h = hv[p];
                acc += w.x*h.x + w.y*h.y + w.z*h.z + w.w*h.w;
            }
            f1s[bb*64 + o] = leakyf_(acc, 0.2f);
        }
        __syncthreads();
        // ---- P2: gates/update(t) || frame(t-1)
        if (t < TT && tid < 522){
            int bb = tid/261, j = tid - bb*261;
            float* hb = bb ? hb1 : hb0;
            const float* s = sums + bb*784;
            float r = sigmoidf_(s[j]);
            float z = sigmoidf_(s[261+j]);
            float n = tanhf(s[522+j] + r*ghn[bb*264 + j]);
            hb[j] = (1.f - z)*n + z*hb[j];
        }
        if (t >= 1 && tid >= 800 && tid < 818){
            int q = tid - 800, bb = q/9, i = q - bb*9;
            float acc = b2[i];
            const float* W = W2 + i*ZD;
            for (int o = 0; o < ZD; o++) acc += W[o]*f1s[bb*64 + o];
            out[(size_t)(b0+bb)*(TT*9) + (t-1)*9 + i] = sigmoidf_(acc);
        }
        __syncthreads();
    }
}

extern "C" void kernel_launch(void* const* d_in, const int* in_sizes, int n_in,
                              void* d_out, int out_size)
{
    const float* input_data = (const float*)d_in[0];
    const float* eps        = (const float*)d_in[1];
    const float* noise_eps  = (const float*)d_in[2];
    const float* proj_W     = (const float*)d_in[3];
    const float* proj_b     = (const float*)d_in[4];
    const float* lstm_Wih   = (const float*)d_in[5];
    const float* lstm_Whh   = (const float*)d_in[6];
    const float* lstm_bih   = (const float*)d_in[7];
    const float* lstm_bhh   = (const float*)d_in[8];
    const float* mu_W       = (const float*)d_in[9];
    const float* mu_b       = (const float*)d_in[10];
    const float* lv_W       = (const float*)d_in[11];
    const float* lv_b       = (const float*)d_in[12];
    const float* fcin_W     = (const float*)d_in[13];
    const float* fcin_b     = (const float*)d_in[14];
    const float* gru_Wih    = (const float*)d_in[15];
    const float* gru_Whh    = (const float*)d_in[16];
    const float* gru_bih    = (const float*)d_in[17];
    const float* gru_bhh    = (const float*)d_in[18];
    const float* jf_W1      = (const float*)d_in[19];
    const float* jf_b1      = (const float*)d_in[20];
    const float* jf_W2      = (const float*)d_in[21];
    const float* jf_b2      = (const float*)d_in[22];
    float* out = (float*)d_out;

    int gemm_smem = 2*2*128*SMSH*2;
    int lstm_smem = 32768*4 + (128 + 512 + 64 + 64 + 64 + 256)*4;
    int gru_smem  = (50176 + 264 + 264 + 2*784 + 2*264 + 128 + TT*8)*4;
    cudaFuncSetAttribute(k_gemm, cudaFuncAttributeMaxDynamicSharedMemorySize, gemm_smem);
    cudaFuncSetAttribute(k_lstm, cudaFuncAttributeMaxDynamicSharedMemorySize, lstm_smem);
    cudaFuncSetAttribute(k_gru,  cudaFuncAttributeMaxDynamicSharedMemorySize, gru_smem);

    k_prep<<<160, 256>>>(lstm_Wih, gru_Whh, jf_W1);
    k_proj<<<BB*TT/8, 512>>>(input_data, proj_W, proj_b);
    dim3 g2(HG/128, TT*BB/128);   // (4, 100)
    k_gemm<<<g2, 256, gemm_smem>>>(lstm_bih, lstm_bhh);
    k_lstm<<<BB, 512, lstm_smem>>>(lstm_Whh, eps, mu_W, mu_b, lv_W, lv_b,
                                   fcin_W, fcin_b, gru_Wih, gru_bih, out);
    k_gru<<<BB/2, 928, gru_smem>>>(noise_eps, gru_Wih, gru_Whh, gru_bhh,
                                   jf_b1, jf_W2, jf_b2, out);
}

// round 12
// speedup vs baseline: 1.0844x; 1.0013x over previous
#include <cuda_runtime.h>
#include <cuda_fp16.h>
#include <math.h>
#include <stdint.h>

#define BB 128
#define TT 100
#define PD 4096
#define HG 512
#define HD 128
#define GH 261
#define GG 783
#define ZD 64
#define XD 256

__device__ __half g_projh[BB*TT*PD];   // fp16 activations (b*T+t, 4096)
__device__ __half g_Wih16[HG*PD];      // fp16 lstm_Wih
__device__ float g_xg[TT*BB*HG];       // (t,b,512)
__device__ float4 g_gWhh4[41*GG];      // gru Whh k=96..259: [p][g]
__device__ float4 g_W1T4[66*ZD];       // jf_W1 packs (zero-padded past 261)
__device__ float g_gxbase[BB*GG];

__device__ __forceinline__ float sigmoidf_(float x){ return 1.0f/(1.0f+expf(-x)); }
__device__ __forceinline__ float leakyf_(float x, float s){ return x >= 0.0f ? x : s*x; }
__device__ __forceinline__ void fma2(unsigned long long& a, unsigned long long w, unsigned long long h){
    asm("fma.rn.f32x2 %0, %1, %2, %0;" : "+l"(a) : "l"(w), "l"(h));
}
__device__ __forceinline__ void cp16(void* s, const void* g){
    unsigned ss = (unsigned)__cvta_generic_to_shared(s);
    asm volatile("cp.async.cg.shared.global [%0], [%1], 16;\n" :: "r"(ss), "l"(g));
}
#define MMA_F16(c, au, bu) \
  asm volatile("mma.sync.aligned.m16n8k16.row.col.f32.f16.f16.f32 " \
    "{%0,%1,%2,%3},{%4,%5,%6,%7},{%8,%9},{%0,%1,%2,%3};\n" \
    : "+f"(c[0]),"+f"(c[1]),"+f"(c[2]),"+f"(c[3]) \
    : "r"(au[0]),"r"(au[1]),"r"(au[2]),"r"(au[3]),"r"(bu[0]),"r"(bu[1]))

// K1: proj (blocks 0..1599) + weight prep (blocks 1600..1759) fused — no
// data dependency between the two tasks, so they overlap in one launch.
__global__ void __launch_bounds__(512) k_proj(const float* __restrict__ pose,
                                              const float* __restrict__ W,
                                              const float* __restrict__ bias,
                                              const float* __restrict__ Wih,
                                              const float* __restrict__ gWhh,
                                              const float* __restrict__ W1)
{
    int tid = threadIdx.x;
    if (blockIdx.x >= 1600){
        // ---- prep path ----
        int i0 = (blockIdx.x - 1600)*512 + tid;
        int st = 160*512;
        for (int i = i0; i < HG*PD; i += st)
            g_Wih16[i] = __float2half_rn(Wih[i]);
        for (int i = i0; i < 41*GG; i += st){
            int p = i / GG, g = i - p*GG;
            const float* r = gWhh + (size_t)g*GH + 96 + 4*p;
            g_gWhh4[i] = make_float4(r[0], r[1], r[2], r[3]);
        }
        for (int i = i0; i < 66*ZD; i += st){
            int p = i >> 6, o = i & 63;
            const float* r = W1 + (size_t)o*GH;
            int k = 4*p;
            float4 v;
            v.x = (k   < GH) ? r[k]   : 0.f;
            v.y = (k+1 < GH) ? r[k+1] : 0.f;
            v.z = (k+2 < GH) ? r[k+2] : 0.f;
            v.w = (k+3 < GH) ? r[k+3] : 0.f;
            g_W1T4[i] = v;
        }
        return;
    }
    // ---- proj path: 8 rows per block ----
    __shared__ float p[8][9];
    int r0 = blockIdx.x*8;
    if (tid < 72) p[tid/9][tid%9] = pose[r0*9 + tid];
    __syncthreads();
#pragma unroll
    for (int i = 0; i < 8; i++){
        int k = tid + i*512;
        const float* w = W + k*9;
        float wv[9];
#pragma unroll
        for (int j = 0; j < 9; j++) wv[j] = w[j];
        float bk = bias[k];
#pragma unroll
        for (int r = 0; r < 8; r++){
            float acc = bk;
#pragma unroll
            for (int j = 0; j < 9; j++) acc += wv[j]*p[r][j];
            g_projh[(size_t)(r0+r)*PD + k] = __float2half_rn(leakyf_(acc, 0.1f));
        }
    }
}

// K2: fp16 mma.sync GEMM: x_gates = proj @ Wih^T + bih + bhh -> (t,b,g)
#define SMSH 72
#define KC 64
__global__ void __launch_bounds__(256, 2) k_gemm(const float* __restrict__ bih,
                                                 const float* __restrict__ bhh)
{
    extern __shared__ __align__(16) char smc[];
    __half* Ash = (__half*)smc;                       // [2][128][72]
    __half* Bsh = (__half*)(smc + 2*128*SMSH*2);      // [2][128][72]
    int tid = threadIdx.x, lane = tid & 31, warp = tid >> 5;
    int bn = blockIdx.x, bm = blockIdx.y;
    const __half* Ag = g_projh + (size_t)bm*128*PD;
    const __half* Bg = g_Wih16 + (size_t)bn*128*PD;
    int wm = warp >> 2, wn = warp & 3;
    float acc[4][4][4];
#pragma unroll
    for (int a = 0; a < 4; a++)
#pragma unroll
        for (int b = 0; b < 4; b++)
#pragma unroll
            for (int c = 0; c < 4; c++) acc[a][b][c] = 0.f;

    for (int i = tid; i < 1024; i += 256){
        int row = i >> 3, sub = i & 7;
        cp16(Ash + row*SMSH + sub*8, Ag + (size_t)row*PD + sub*8);
    }
    for (int i = tid; i < 1024; i += 256){
        int row = i >> 3, sub = i & 7;
        cp16(Bsh + row*SMSH + sub*8, Bg + (size_t)row*PD + sub*8);
    }
    asm volatile("cp.async.commit_group;\n");

    for (int c = 0; c < PD/KC; c++){
        int buf = c & 1;
        if (c+1 < PD/KC){
            int nb = buf^1;
            int kof = (c+1)*KC;
            for (int i = tid; i < 1024; i += 256){
                int row = i >> 3, sub = i & 7;
                cp16(Ash + nb*128*SMSH + row*SMSH + sub*8, Ag + (size_t)row*PD + kof + sub*8);
            }
            for (int i = tid; i < 1024; i += 256){
                int row = i >> 3, sub = i & 7;
                cp16(Bsh + nb*128*SMSH + row*SMSH + sub*8, Bg + (size_t)row*PD + kof + sub*8);
            }
        }
        asm volatile("cp.async.commit_group;\n");
        asm volatile("cp.async.wait_group 1;\n");
        __syncthreads();
        const uint32_t* A = (const uint32_t*)(Ash + buf*128*SMSH);
        const uint32_t* B = (const uint32_t*)(Bsh + buf*128*SMSH);
#pragma unroll
        for (int kk = 0; kk < 4; kk++){
            int kw = kk*8 + (lane & 3);
            uint32_t au[4][4], bu[4][2];
#pragma unroll
            for (int mt = 0; mt < 4; mt++){
                int r = wm*64 + mt*16 + (lane>>2);
                au[mt][0] = A[r*36 + kw];
                au[mt][1] = A[(r+8)*36 + kw];
                au[mt][2] = A[r*36 + kw + 4];
                au[mt][3] = A[(r+8)*36 + kw + 4];
            }
#pragma unroll
            for (int nt = 0; nt < 4; nt++){
                int n = wn*32 + nt*8 + (lane>>2);
                bu[nt][0] = B[n*36 + kw];
                bu[nt][1] = B[n*36 + kw + 4];
            }
#pragma unroll
            for (int mt = 0; mt < 4; mt++)
#pragma unroll
                for (int nt = 0; nt < 4; nt++)
                    MMA_F16(acc[mt][nt], au[mt], bu[nt]);
        }
        __syncthreads();
    }
#pragma unroll
    for (int mt = 0; mt < 4; mt++){
#pragma unroll
        for (int nt = 0; nt < 4; nt++){
            int col = bn*128 + wn*32 + nt*8 + (lane&3)*2;
            float bs0 = bih[col]   + bhh[col];
            float bs1 = bih[col+1] + bhh[col+1];
            int r0 = bm*128 + wm*64 + mt*16 + (lane>>2);
            int b0i = r0/TT, t0 = r0 - b0i*TT;
            *(float2*)(g_xg + (size_t)t0*(BB*HG) + b0i*HG + col) =
                make_float2(acc[mt][nt][0]+bs0, acc[mt][nt][1]+bs1);
            int r1 = r0 + 8;
            int b1i = r1/TT, t1 = r1 - b1i*TT;
            *(float2*)(g_xg + (size_t)t1*(BB*HG) + b1i*HG + col) =
                make_float2(acc[mt][nt][2]+bs0, acc[mt][nt][3]+bs1);
        }
    }
}

// K3: LSTM scan nb=1 (128 blocks), 2-sync gate phase + fused head
__global__ void __launch_bounds__(512) k_lstm(
    const float* __restrict__ Whh,
    const float* __restrict__ eps,
    const float* __restrict__ muW, const float* __restrict__ mub,
    const float* __restrict__ lvW, const float* __restrict__ lvb,
    const float* __restrict__ fcW, const float* __restrict__ fcb,
    const float* __restrict__ gWih, const float* __restrict__ gbih,
    float* __restrict__ out)
{
    extern __shared__ float sm[];
    ulonglong2* wsu2 = (ulonglong2*)sm;          // [16][512]: k=64..127
    float* hs = sm + 32768;                      // 128
    float* gs = hs + 128;                        // 512
    float* mu_s = gs + 512;                      // 64
    float* lv_s = mu_s + 64;                     // 64
    float* emb  = lv_s + 64;                     // 64
    float* xs   = emb + 64;                      // 256
    int tid = threadIdx.x, b = blockIdx.x;

    const ulonglong2* wrow = (const ulonglong2*)(Whh + (size_t)tid*HD);
    unsigned long long wr2[32];
#pragma unroll
    for (int i = 0; i < 16; i++){
        ulonglong2 v = wrow[i];
        wr2[2*i] = v.x; wr2[2*i+1] = v.y;
    }
#pragma unroll
    for (int i = 0; i < 16; i++) wsu2[i*512 + tid] = wrow[16+i];
    if (tid < HD) hs[tid] = 0.f;
    float c = 0.f;
    __syncthreads();
    const float* xg = g_xg + b*HG + tid;
    float xcur = xg[0];
    for (int t = 0; t < TT; t++){
        float xnext = (t < TT-1) ? xg[(size_t)(t+1)*(BB*HG)] : 0.f;
        const ulonglong2* H2 = (const ulonglong2*)hs;
        unsigned long long a2 = 0ull, c2 = 0ull, d2 = 0ull, e2 = 0ull;
#pragma unroll
        for (int i = 0; i < 8; i++){
            ulonglong2 h0 = H2[2*i], h1 = H2[2*i+1];
            fma2(a2, wr2[4*i],   h0.x);
            fma2(c2, wr2[4*i+1], h0.y);
            fma2(d2, wr2[4*i+2], h1.x);
            fma2(e2, wr2[4*i+3], h1.y);
        }
#pragma unroll
        for (int i = 0; i < 8; i++){
            ulonglong2 w0 = wsu2[(2*i)*512 + tid];
            ulonglong2 w1 = wsu2[(2*i+1)*512 + tid];
            ulonglong2 h0 = H2[16+2*i], h1 = H2[17+2*i];
            fma2(a2, w0.x, h0.x);
            fma2(c2, w0.y, h0.y);
            fma2(d2, w1.x, h1.x);
            fma2(e2, w1.y, h1.y);
        }
        float a0,a1,b0,b1,d0,d1,e0,e1;
        asm("mov.b64 {%0,%1}, %2;" : "=f"(a0), "=f"(a1) : "l"(a2));
        asm("mov.b64 {%0,%1}, %2;" : "=f"(b0), "=f"(b1) : "l"(c2));
        asm("mov.b64 {%0,%1}, %2;" : "=f"(d0), "=f"(d1) : "l"(d2));
        asm("mov.b64 {%0,%1}, %2;" : "=f"(e0), "=f"(e1) : "l"(e2));
        gs[tid] = xcur + ((a0+a1) + (b0+b1)) + ((d0+d1) + (e0+e1));
        __syncthreads();
        if (tid < HD){
            float ii = sigmoidf_(gs[tid]);
            float ff = sigmoidf_(gs[HD+tid]);
            float gg = tanhf(gs[2*HD+tid]);
            float oo = sigmoidf_(gs[3*HD+tid]);
            c = ff*c + ii*gg;
            hs[tid] = oo*tanhf(c);
        }
        __syncthreads();
        xcur = xnext;
    }
    // ---- fused head (batch b) ----
    if (tid < 2*ZD){
        int o = tid & 63;
        const float* W = (tid < ZD) ? (muW + o*HD) : (lvW + o*HD);
        float acc = (tid < ZD) ? mub[o] : lvb[o];
        for (int k = 0; k < HD; k++) acc += W[k]*hs[k];
        acc = leakyf_(acc, 0.1f);
        if (tid < ZD) mu_s[o] = acc;
        else          lv_s[o] = fminf(10.f, fmaxf(-10.f, acc));
    }
    __syncthreads();
    if (tid < ZD){
        float m = mu_s[tid], lv = lv_s[tid];
        out[BB*TT*9 + b*ZD + tid] = m;
        out[BB*TT*9 + BB*ZD + b*ZD + tid] = lv;
        emb[tid] = m + eps[b*ZD + tid]*expf(0.5f*lv);
    }
    __syncthreads();
    if (tid < XD){
        float acc = fcb[tid];
        const float* W = fcW + tid*ZD;
        for (int k = 0; k < ZD; k++) acc += W[k]*emb[k];
        xs[tid] = acc;
    }
    __syncthreads();
    for (int g = tid; g < GG; g += 512){
        float acc = gbih[g];
        const float* W = gWih + (size_t)g*GH;
        for (int k = 0; k < XD; k++) acc += W[k]*xs[k];
        g_gxbase[(size_t)b*GG + g] = acc;
    }
}

// K5: GRU scan + pipelined jf head. 928 threads, 2 batches/block, 2 syncs/step.
__global__ void __launch_bounds__(928) k_gru(
    const float* __restrict__ noise_eps,
    const float* __restrict__ gWih, const float* __restrict__ gWhh,
    const float* __restrict__ gbhh,
    const float* __restrict__ b1,
    const float* __restrict__ W2, const float* __restrict__ b2,
    float* __restrict__ out)
{
    extern __shared__ float sm[];
    ulonglong2* wsA = (ulonglong2*)sm;   // [16][784]: k=32..95 pair-pairs
    float* hb0  = sm + 50176;            // 264 (zero-padded)
    float* hb1  = hb0 + 264;
    float* sums = hb1 + 264;             // [2][784]
    float* ghn  = sums + 2*784;          // [2][264]
    float* f1s  = ghn + 2*264;           // [2][64]
    float* nsAll= f1s + 128;             // [TT][8]
    int tid = threadIdx.x;
    int b0 = blockIdx.x*2;

    for (int j = tid; j < 528; j += 928) hb0[j] = 0.f;
    for (int j = tid; j < TT*8; j += 928){
        int t = j >> 3, r = j & 7, bb = r >> 2, jj = r & 3;
        nsAll[j] = noise_eps[t*(BB*4) + (b0+bb)*4 + jj] * 0.1f;
    }

    unsigned long long wr2[16];
    float w260=0,wn0=0,wn1=0,wn2=0,wn3=0,wt=0,bh=0,gx0b=0,gx1b=0;
    if (tid < GG){
        const float* row = gWhh + (size_t)tid*GH;
#pragma unroll
        for (int i = 0; i < 16; i++)
            asm("mov.b64 %0, {%1,%2};" : "=l"(wr2[i]) : "f"(row[2*i]), "f"(row[2*i+1]));
#pragma unroll
        for (int i = 0; i < 16; i++){
            ulonglong2 w;
            asm("mov.b64 %0, {%1,%2};" : "=l"(w.x) : "f"(row[32+4*i]), "f"(row[33+4*i]));
            asm("mov.b64 %0, {%1,%2};" : "=l"(w.y) : "f"(row[34+4*i]), "f"(row[35+4*i]));
            wsA[i*784 + tid] = w;
        }
        w260 = row[260];
        const float* Wi = gWih + (size_t)tid*GH;
        wn0=Wi[256]; wn1=Wi[257]; wn2=Wi[258]; wn3=Wi[259]; wt=Wi[260];
        bh = gbhh[tid];
        gx0b = g_gxbase[b0*GG + tid];
        gx1b = g_gxbase[(b0+1)*GG + tid];
    }
    __syncthreads();
    const float inv = 1.0f/(float)(TT-1);
    for (int t = 0; t <= TT; t++){
        // ---- P1: matvec(t) || f1-head(t-1)
        if (t < TT && tid < GG){
            const float* nsp = nsAll + t*8;
            float tv = (float)t * inv;
            float gx0 = gx0b + wn0*nsp[0]+wn1*nsp[1]+wn2*nsp[2]+wn3*nsp[3] + wt*tv;
            float gx1 = gx1b + wn0*nsp[4]+wn1*nsp[5]+wn2*nsp[6]+wn3*nsp[7] + wt*tv;
            unsigned long long a0p = 0ull, a1p = 0ull;
            const ulonglong2* H0 = (const ulonglong2*)hb0;
            const ulonglong2* H1 = (const ulonglong2*)hb1;
#pragma unroll
            for (int i = 0; i < 8; i++){
                ulonglong2 h0 = H0[i], h1 = H1[i];
                fma2(a0p, wr2[2*i],   h0.x);  fma2(a1p, wr2[2*i],   h1.x);
                fma2(a0p, wr2[2*i+1], h0.y);  fma2(a1p, wr2[2*i+1], h1.y);
            }
#pragma unroll
            for (int i = 0; i < 16; i++){
                ulonglong2 w = wsA[i*784 + tid];
                ulonglong2 h0 = H0[8+i], h1 = H1[8+i];
                fma2(a0p, w.x, h0.x);  fma2(a1p, w.x, h1.x);
                fma2(a0p, w.y, h0.y);  fma2(a1p, w.y, h1.y);
            }
            const ulonglong2* wp = (const ulonglong2*)g_gWhh4 + tid;
#pragma unroll 8
            for (int p = 0; p < 41; p++){
                ulonglong2 w = wp[(size_t)p*GG];
                ulonglong2 h0 = H0[24+p], h1 = H1[24+p];
                fma2(a0p, w.x, h0.x);  fma2(a1p, w.x, h1.x);
                fma2(a0p, w.y, h0.y);  fma2(a1p, w.y, h1.y);
            }
            float s00,s01,s10,s11;
            asm("mov.b64 {%0,%1}, %2;" : "=f"(s00), "=f"(s01) : "l"(a0p));
            asm("mov.b64 {%0,%1}, %2;" : "=f"(s10), "=f"(s11) : "l"(a1p));
            float gh0 = bh + (s00+s01) + w260*hb0[260];
            float gh1 = bh + (s10+s11) + w260*hb1[260];
            float v0 = gx0 + gh0, v1 = gx1 + gh1;
            if (tid >= 522){
                v0 = gx0; v1 = gx1;
                ghn[tid-522] = gh0; ghn[264 + tid-522] = gh1;
            }
            sums[tid] = v0; sums[784 + tid] = v1;
        }
        if (t >= 1 && tid >= 800){
            int q = tid - 800, bb = q >> 6, o = q & 63;
            const float4* hv = (const float4*)(bb ? hb1 : hb0);
            const float4* Wv = g_W1T4 + o;
            float acc = b1[o];
#pragma unroll
            for (int p = 0; p < 66; p++){
                float4 w = Wv[p*ZD];
                float4 h = hv[p];
                acc += w.x*h.x + w.y*h.y + w.z*h.z + w.w*h.w;
            }
            f1s[bb*64 + o] = leakyf_(acc, 0.2f);
        }
        __syncthreads();
        // ---- P2: gates/update(t) || frame(t-1)
        if (t < TT && tid < 522){
            int bb = tid/261, j = tid - bb*261;
            float* hb = bb ? hb1 : hb0;
            const float* s = sums + bb*784;
            float r = sigmoidf_(s[j]);
            float z = sigmoidf_(s[261+j]);
            float n = tanhf(s[522+j] + r*ghn[bb*264 + j]);
            hb[j] = (1.f - z)*n + z*hb[j];
        }
        if (t >= 1 && tid >= 800 && tid < 818){
            int q = tid - 800, bb = q/9, i = q - bb*9;
            float acc = b2[i];
            const float* W = W2 + i*ZD;
            for (int o = 0; o < ZD; o++) acc += W[o]*f1s[bb*64 + o];
            out[(size_t)(b0+bb)*(TT*9) + (t-1)*9 + i] = sigmoidf_(acc);
        }
        __syncthreads();
    }
}

extern "C" void kernel_launch(void* const* d_in, const int* in_sizes, int n_in,
                              void* d_out, int out_size)
{
    const float* input_data = (const float*)d_in[0];
    const float* eps        = (const float*)d_in[1];
    const float* noise_eps  = (const float*)d_in[2];
    const float* proj_W     = (const float*)d_in[3];
    const float* proj_b     = (const float*)d_in[4];
    const float* lstm_Wih   = (const float*)d_in[5];
    const float* lstm_Whh   = (const float*)d_in[6];
    const float* lstm_bih   = (const float*)d_in[7];
    const float* lstm_bhh   = (const float*)d_in[8];
    const float* mu_W       = (const float*)d_in[9];
    const float* mu_b       = (const float*)d_in[10];
    const float* lv_W       = (const float*)d_in[11];
    const float* lv_b       = (const float*)d_in[12];
    const float* fcin_W     = (const float*)d_in[13];
    const float* fcin_b     = (const float*)d_in[14];
    const float* gru_Wih    = (const float*)d_in[15];
    const float* gru_Whh    = (const float*)d_in[16];
    const float* gru_bih    = (const float*)d_in[17];
    const float* gru_bhh    = (const float*)d_in[18];
    const float* jf_W1      = (const float*)d_in[19];
    const float* jf_b1      = (const float*)d_in[20];
    const float* jf_W2      = (const float*)d_in[21];
    const float* jf_b2      = (const float*)d_in[22];
    float* out = (float*)d_out;

    int gemm_smem = 2*2*128*SMSH*2;
    int lstm_smem = 32768*4 + (128 + 512 + 64 + 64 + 64 + 256)*4;
    int gru_smem  = (50176 + 264 + 264 + 2*784 + 2*264 + 128 + TT*8)*4;
    cudaFuncSetAttribute(k_gemm, cudaFuncAttributeMaxDynamicSharedMemorySize, gemm_smem);
    cudaFuncSetAttribute(k_lstm, cudaFuncAttributeMaxDynamicSharedMemorySize, lstm_smem);
    cudaFuncSetAttribute(k_gru,  cudaFuncAttributeMaxDynamicSharedMemorySize, gru_smem);

    k_proj<<<1760, 512>>>(input_data, proj_W, proj_b,
                          lstm_Wih, gru_Whh, jf_W1);
    dim3 g2(HG/128, TT*BB/128);   // (4, 100)
    k_gemm<<<g2, 256, gemm_smem>>>(lstm_bih, lstm_bhh);
    k_lstm<<<BB, 512, lstm_smem>>>(lstm_Whh, eps, mu_W, mu_b, lv_W, lv_b,
                                   fcin_W, fcin_b, gru_Wih, gru_bih, out);
    k_gru<<<BB/2, 928, gru_smem>>>(noise_eps, gru_Wih, gru_Whh, gru_bhh,
                                   jf_b1, jf_W2, jf_b2, out);
}